// round 3
// baseline (speedup 1.0000x reference)
#include <cuda_runtime.h>
#include <cuda_bf16.h>
#include <cstdint>

// ---------------- problem dims ----------------
#define NTOK 8192
#define TOPK 2
#define NEXP 8
#define MM   16384   // expert-sorted rows
#define KK   512
#define NN   1024

// A2: [M][1024] bf16 : cols [0,512)=hi(input), [512,1024)=lo residual
// B2: [E][1024][1024] bf16 : rows [0,512)=hi(w[e][k][n]), [512,1024)=lo
static __device__ __align__(128) __nv_bfloat16 g_A2[(size_t)MM * 1024];          // 32 MiB
static __device__ __align__(128) __nv_bfloat16 g_B2[(size_t)NEXP * 1024 * 1024]; // 16 MiB
static __device__ __align__(128) float         g_y [(size_t)MM * NN];            // 64 MiB

// ---------------- helpers ----------------
__device__ __forceinline__ uint32_t smem_u32(const void* p) {
    uint32_t a;
    asm("{ .reg .u64 t; cvta.to.shared.u64 t, %1; cvt.u32.u64 %0, t; }"
        : "=r"(a) : "l"(p));
    return a;
}
__device__ __forceinline__ void cp16(uint32_t dst, const void* src) {
    asm volatile("cp.async.cg.shared.global [%0], [%1], 16;"
                 :: "r"(dst), "l"(src) : "memory");
}
__device__ __forceinline__ void cp_commit() {
    asm volatile("cp.async.commit_group;" ::: "memory");
}
template <int N_>
__device__ __forceinline__ void cp_wait() {
    asm volatile("cp.async.wait_group %0;" :: "n"(N_) : "memory");
}
__device__ __forceinline__ void ldsm_x4(uint32_t* r, uint32_t addr) {
    asm volatile("ldmatrix.sync.aligned.m8n8.x4.shared.b16 {%0,%1,%2,%3}, [%4];"
                 : "=r"(r[0]), "=r"(r[1]), "=r"(r[2]), "=r"(r[3]) : "r"(addr));
}
__device__ __forceinline__ void ldsm_x4_t(uint32_t* r, uint32_t addr) {
    asm volatile("ldmatrix.sync.aligned.m8n8.x4.trans.shared.b16 {%0,%1,%2,%3}, [%4];"
                 : "=r"(r[0]), "=r"(r[1]), "=r"(r[2]), "=r"(r[3]) : "r"(addr));
}
__device__ __forceinline__ void mma16816(float* c, const uint32_t* a, const uint32_t* b) {
    asm volatile(
        "mma.sync.aligned.m16n8k16.row.col.f32.bf16.bf16.f32 "
        "{%0,%1,%2,%3}, {%4,%5,%6,%7}, {%8,%9}, {%0,%1,%2,%3};"
        : "+f"(c[0]), "+f"(c[1]), "+f"(c[2]), "+f"(c[3])
        : "r"(a[0]), "r"(a[1]), "r"(a[2]), "r"(a[3]), "r"(b[0]), "r"(b[1]));
}
__device__ __forceinline__ uint32_t pack_bf2(__nv_bfloat16 x, __nv_bfloat16 y) {
    __nv_bfloat162 t = __halves2bfloat162(x, y);
    return *reinterpret_cast<uint32_t*>(&t);
}

// ---------------- kernel 1: input fp32 -> hi|lo halves ----------------------
__global__ void prep_input_kernel(const float* __restrict__ in) {
    size_t idx  = (size_t)blockIdx.x * blockDim.x + threadIdx.x; // MM*KK/4
    size_t base = idx * 4;
    float4 v = *reinterpret_cast<const float4*>(in + base);
    int m = (int)(base / KK);
    int k = (int)(base % KK);
    float f[4] = {v.x, v.y, v.z, v.w};
    __nv_bfloat16 hi[4], lo[4];
#pragma unroll
    for (int i = 0; i < 4; i++) {
        hi[i] = __float2bfloat16_rn(f[i]);
        lo[i] = __float2bfloat16_rn(f[i] - __bfloat162float(hi[i]));
    }
    uint2 h = make_uint2(pack_bf2(hi[0], hi[1]), pack_bf2(hi[2], hi[3]));
    uint2 l = make_uint2(pack_bf2(lo[0], lo[1]), pack_bf2(lo[2], lo[3]));
    *reinterpret_cast<uint2*>(g_A2 + (size_t)m * 1024 + k)       = h;
    *reinterpret_cast<uint2*>(g_A2 + (size_t)m * 1024 + 512 + k) = l;
}

// ---------------- kernel 2: weight fp32 [E,K,N] -> hi|lo [E,1024,N] ---------
__global__ void prep_weight_kernel(const float* __restrict__ w) {
    size_t idx  = (size_t)blockIdx.x * blockDim.x + threadIdx.x; // E*K*N/4
    size_t base = idx * 4;
    float4 v = *reinterpret_cast<const float4*>(w + base);
    int n  = (int)(base % NN);
    int ek = (int)(base / NN);          // e*512 + k
    int e  = ek >> 9;
    int k  = ek & 511;
    float f[4] = {v.x, v.y, v.z, v.w};
    __nv_bfloat16 hi[4], lo[4];
#pragma unroll
    for (int i = 0; i < 4; i++) {
        hi[i] = __float2bfloat16_rn(f[i]);
        lo[i] = __float2bfloat16_rn(f[i] - __bfloat162float(hi[i]));
    }
    uint2 h = make_uint2(pack_bf2(hi[0], hi[1]), pack_bf2(hi[2], hi[3]));
    uint2 l = make_uint2(pack_bf2(lo[0], lo[1]), pack_bf2(lo[2], lo[3]));
    size_t eb = (size_t)e << 20;        // e * 1024 * 1024
    *reinterpret_cast<uint2*>(g_B2 + eb + (size_t)k * 1024 + n)         = h;
    *reinterpret_cast<uint2*>(g_B2 + eb + (size_t)(512 + k) * 1024 + n) = l;
}

// ---------------- kernel 3: HMMA grouped GEMM -> g_y (scaled) ---------------
// CTA tile 128(M) x 256(N), 8 warps (2x4 of 64x64), K-step 32 orig K.
// SMEM/stage: Ahi 8K | Alo 8K | Bhi 16K | Blo 16K = 48KB; 3 stages = 144KB.
#define STG_BYTES 49152u
#define OA_HI 0u
#define OA_LO 8192u
#define OB_HI 16384u
#define OB_LO 32768u
#define GEMM_SMEM (3u * STG_BYTES)

// A smem: [128 rows][32 bf16], 64B rows, quad q(0..3): phys = row*64 + ((q^((row>>1)&3))<<4)
// B smem: [32 rows(k)][256 bf16(n)], 512B rows, quad q(0..31): phys = row*512 + ((q^(row&7))<<4)
__global__ void __launch_bounds__(256, 1) moe_gemm_kernel(
    const int*   __restrict__ splits,
    const float* __restrict__ in_scale,
    const float* __restrict__ w_scale,
    const float* __restrict__ ovs)
{
    extern __shared__ char smem[];
    const uint32_t sb = smem_u32(smem);
    const int tid  = threadIdx.x;
    const int lane = tid & 31;
    const int wid  = tid >> 5;
    const int wm   = (wid & 1) * 64;    // warp M offset in tile
    const int wn   = (wid >> 1) * 64;   // warp N offset in tile

    const int bn = blockIdx.x & 3;
    const int bm = blockIdx.x >> 2;
    const int m0 = bm * 128, n0 = bn * 256;

    // expert for this row tile (splits sum to MM; tiles don't straddle here)
    int e = 0;
    {
        int acc = 0;
#pragma unroll
        for (int i = 0; i < NEXP; i++) { acc += splits[i]; if (m0 < acc) { e = i; break; } }
    }
    const __nv_bfloat16* Ab = g_A2 + (size_t)m0 * 1024;
    const __nv_bfloat16* Bb = g_B2 + ((size_t)e << 20) + n0;

    // ---- stage loader ----
    auto load_stage = [&](int c) {            // c = k-step index 0..15
        const uint32_t s = sb + (uint32_t)(c % 3) * STG_BYTES;
        const int koff = c * 32;
        // A: 512 x16B units per half; 2 per thread
#pragma unroll
        for (int j = 0; j < 2; j++) {
            int u = tid + j * 256;
            int row = u >> 2, q = u & 3;
            uint32_t d = (uint32_t)(row * 64 + ((q ^ ((row >> 1) & 3)) << 4));
            const __nv_bfloat16* src = Ab + (size_t)row * 1024 + koff + q * 8;
            cp16(s + OA_HI + d, src);
            cp16(s + OA_LO + d, src + 512);
        }
        // B: 1024 x16B units per half; 4 per thread
#pragma unroll
        for (int j = 0; j < 4; j++) {
            int u = tid + j * 256;
            int row = u >> 5, q = u & 31;
            uint32_t d = (uint32_t)(row * 512 + ((q ^ (row & 7)) << 4));
            const __nv_bfloat16* src = Bb + (size_t)(koff + row) * 1024 + q * 8;
            cp16(s + OB_HI + d, src);
            cp16(s + OB_LO + d, src + (size_t)512 * 1024);
        }
        cp_commit();
    };

    float c[4][8][4];
#pragma unroll
    for (int i = 0; i < 4; i++)
#pragma unroll
        for (int j = 0; j < 8; j++)
#pragma unroll
            for (int q = 0; q < 4; q++) c[i][j][q] = 0.f;

    load_stage(0);
    load_stage(1);

#pragma unroll 1
    for (int ks = 0; ks < 16; ks++) {
        cp_wait<1>();
        __syncthreads();
        if (ks + 2 < 16) load_stage(ks + 2);

        const uint32_t s = sb + (uint32_t)(ks % 3) * STG_BYTES;
#pragma unroll
        for (int kh = 0; kh < 32; kh += 16) {
            // ---- A fragments (hi, lo) ----
            uint32_t a_hi[4][4], a_lo[4][4];
            {
                int row = (lane & 15);
                int kq  = (kh >> 3) + (lane >> 4);
#pragma unroll
                for (int i = 0; i < 4; i++) {
                    int r = wm + i * 16 + row;
                    uint32_t ad = (uint32_t)(r * 64 + ((kq ^ ((r >> 1) & 3)) << 4));
                    ldsm_x4(a_hi[i], s + OA_HI + ad);
                    ldsm_x4(a_lo[i], s + OA_LO + ad);
                }
            }
            // ---- B hi fragments, then hi*hi and lo*hi ----
            uint32_t b[4][4];   // j-th x4 covers n-tiles 2j, 2j+1
            {
                int k  = kh + (lane & 15);
                int nqb = (wn >> 3) + (lane >> 4);
#pragma unroll
                for (int j = 0; j < 4; j++) {
                    int nq = nqb + j * 2;
                    uint32_t ad = (uint32_t)(k * 512 + ((nq ^ (k & 7)) << 4));
                    ldsm_x4_t(b[j], s + OB_HI + ad);
                }
            }
#pragma unroll
            for (int i = 0; i < 4; i++)
#pragma unroll
                for (int j = 0; j < 8; j++) {
                    mma16816(c[i][j], a_hi[i], &b[j >> 1][(j & 1) * 2]);
                }
#pragma unroll
            for (int i = 0; i < 4; i++)
#pragma unroll
                for (int j = 0; j < 8; j++) {
                    mma16816(c[i][j], a_lo[i], &b[j >> 1][(j & 1) * 2]);
                }
            // ---- B lo fragments, then hi*lo ----
            {
                int k  = kh + (lane & 15);
                int nqb = (wn >> 3) + (lane >> 4);
#pragma unroll
                for (int j = 0; j < 4; j++) {
                    int nq = nqb + j * 2;
                    uint32_t ad = (uint32_t)(k * 512 + ((nq ^ (k & 7)) << 4));
                    ldsm_x4_t(b[j], s + OB_LO + ad);
                }
            }
#pragma unroll
            for (int i = 0; i < 4; i++)
#pragma unroll
                for (int j = 0; j < 8; j++) {
                    mma16816(c[i][j], a_hi[i], &b[j >> 1][(j & 1) * 2]);
                }
        }
    }

    // ---- epilogue: scale rows, store fp32 scratch ----
    const float gs = in_scale[0] * w_scale[e];
#pragma unroll
    for (int i = 0; i < 4; i++) {
        int r0 = m0 + wm + i * 16 + (lane >> 2);
        float s0 = gs * ovs[r0];
        float s1 = gs * ovs[r0 + 8];
        float* y0 = g_y + (size_t)r0 * NN + n0 + wn + (lane & 3) * 2;
        float* y1 = y0 + (size_t)8 * NN;
#pragma unroll
        for (int j = 0; j < 8; j++) {
            float2 v0 = make_float2(c[i][j][0] * s0, c[i][j][1] * s0);
            float2 v1 = make_float2(c[i][j][2] * s1, c[i][j][3] * s1);
            *reinterpret_cast<float2*>(y0 + j * 8) = v0;
            *reinterpret_cast<float2*>(y1 + j * 8) = v1;
        }
    }
}

// ---------------- kernel 4: topk gather-reduce ------------------------------
__global__ void gather_kernel(const int* __restrict__ sidx,
                              float* __restrict__ out) {
    int t  = blockIdx.x;
    int n4 = threadIdx.x;
    int s0 = sidx[t * TOPK + 0];
    int s1 = sidx[t * TOPK + 1];
    const float4 a = *reinterpret_cast<const float4*>(g_y + (size_t)s0 * NN + n4 * 4);
    const float4 b = *reinterpret_cast<const float4*>(g_y + (size_t)s1 * NN + n4 * 4);
    float4 o;
    o.x = a.x + b.x; o.y = a.y + b.y; o.z = a.z + b.z; o.w = a.w + b.w;
    *reinterpret_cast<float4*>(out + (size_t)t * NN + n4 * 4) = o;
}

// ---------------- launch ----------------
extern "C" void kernel_launch(void* const* d_in, const int* in_sizes, int n_in,
                              void* d_out, int out_size) {
    (void)in_sizes; (void)n_in; (void)out_size;
    const float* input    = (const float*)d_in[0];
    const float* weight   = (const float*)d_in[1];
    const int*   splits   = (const int*)  d_in[2];
    const int*   scatter  = (const int*)  d_in[3];
    const float* in_scale = (const float*)d_in[4];
    const float* w_scale  = (const float*)d_in[5];
    const float* ovs      = (const float*)d_in[6];
    float*       out      = (float*)d_out;

    static bool attr_set = false;
    if (!attr_set) {
        cudaFuncSetAttribute(moe_gemm_kernel,
                             cudaFuncAttributeMaxDynamicSharedMemorySize,
                             (int)GEMM_SMEM);
        attr_set = true;
    }

    prep_input_kernel <<<(MM * KK / 4) / 256, 256>>>(input);
    prep_weight_kernel<<<(NEXP * KK * NN / 4) / 256, 256>>>(weight);
    moe_gemm_kernel   <<<(MM / 128) * (NN / 256), 256, GEMM_SMEM>>>(
        splits, in_scale, w_scale, ovs);
    gather_kernel     <<<NTOK, 256>>>(scatter, out);
}

// round 5
// speedup vs baseline: 1.1287x; 1.1287x over previous
#include <cuda_runtime.h>
#include <cuda_bf16.h>
#include <cstdint>

// ---------------- problem dims ----------------
#define NTOK 8192
#define TOPK 2
#define NEXP 8
#define MM   16384   // expert-sorted rows
#define KK   512
#define NN   1024

// A2: [M][1024] bf16 : cols [0,512)=hi(input), [512,1024)=lo residual
// B2: [E][1024][1024] bf16 : rows [0,512)=hi(w[e][k][n]), [512,1024)=lo
static __device__ __align__(128) __nv_bfloat16 g_A2[(size_t)MM * 1024];          // 32 MiB
static __device__ __align__(128) __nv_bfloat16 g_B2[(size_t)NEXP * 1024 * 1024]; // 16 MiB
static __device__ __align__(128) float         g_y [(size_t)MM * NN];            // 64 MiB

// ---------------- helpers ----------------
__device__ __forceinline__ uint32_t smem_u32(const void* p) {
    uint32_t a;
    asm("{ .reg .u64 t; cvta.to.shared.u64 t, %1; cvt.u32.u64 %0, t; }"
        : "=r"(a) : "l"(p));
    return a;
}
__device__ __forceinline__ void cp16(uint32_t dst, const void* src) {
    asm volatile("cp.async.cg.shared.global [%0], [%1], 16;"
                 :: "r"(dst), "l"(src) : "memory");
}
__device__ __forceinline__ void cp_commit() {
    asm volatile("cp.async.commit_group;" ::: "memory");
}
template <int N_>
__device__ __forceinline__ void cp_wait() {
    asm volatile("cp.async.wait_group %0;" :: "n"(N_) : "memory");
}
__device__ __forceinline__ void ldsm_x4(uint32_t* r, uint32_t addr) {
    asm volatile("ldmatrix.sync.aligned.m8n8.x4.shared.b16 {%0,%1,%2,%3}, [%4];"
                 : "=r"(r[0]), "=r"(r[1]), "=r"(r[2]), "=r"(r[3]) : "r"(addr));
}
__device__ __forceinline__ void ldsm_x4_t(uint32_t* r, uint32_t addr) {
    asm volatile("ldmatrix.sync.aligned.m8n8.x4.trans.shared.b16 {%0,%1,%2,%3}, [%4];"
                 : "=r"(r[0]), "=r"(r[1]), "=r"(r[2]), "=r"(r[3]) : "r"(addr));
}
__device__ __forceinline__ void mma16816(float* c, const uint32_t* a, const uint32_t* b) {
    asm volatile(
        "mma.sync.aligned.m16n8k16.row.col.f32.bf16.bf16.f32 "
        "{%0,%1,%2,%3}, {%4,%5,%6,%7}, {%8,%9}, {%0,%1,%2,%3};"
        : "+f"(c[0]), "+f"(c[1]), "+f"(c[2]), "+f"(c[3])
        : "r"(a[0]), "r"(a[1]), "r"(a[2]), "r"(a[3]), "r"(b[0]), "r"(b[1]));
}
__device__ __forceinline__ uint32_t pack_bf2(__nv_bfloat16 x, __nv_bfloat16 y) {
    __nv_bfloat162 t = __halves2bfloat162(x, y);
    return *reinterpret_cast<uint32_t*>(&t);
}

// ---------------- kernel 1: input fp32 -> hi|lo halves ----------------------
__global__ void prep_input_kernel(const float* __restrict__ in) {
    size_t idx  = (size_t)blockIdx.x * blockDim.x + threadIdx.x; // MM*KK/4
    size_t base = idx * 4;
    float4 v = *reinterpret_cast<const float4*>(in + base);
    int m = (int)(base / KK);
    int k = (int)(base % KK);
    float f[4] = {v.x, v.y, v.z, v.w};
    __nv_bfloat16 hi[4], lo[4];
#pragma unroll
    for (int i = 0; i < 4; i++) {
        hi[i] = __float2bfloat16_rn(f[i]);
        lo[i] = __float2bfloat16_rn(f[i] - __bfloat162float(hi[i]));
    }
    uint2 h = make_uint2(pack_bf2(hi[0], hi[1]), pack_bf2(hi[2], hi[3]));
    uint2 l = make_uint2(pack_bf2(lo[0], lo[1]), pack_bf2(lo[2], lo[3]));
    *reinterpret_cast<uint2*>(g_A2 + (size_t)m * 1024 + k)       = h;
    *reinterpret_cast<uint2*>(g_A2 + (size_t)m * 1024 + 512 + k) = l;
}

// ---------------- kernel 2: weight fp32 [E,K,N] -> hi|lo [E,1024,N] ---------
__global__ void prep_weight_kernel(const float* __restrict__ w) {
    size_t idx  = (size_t)blockIdx.x * blockDim.x + threadIdx.x; // E*K*N/4
    size_t base = idx * 4;
    float4 v = *reinterpret_cast<const float4*>(w + base);
    int n  = (int)(base % NN);
    int ek = (int)(base / NN);          // e*512 + k
    int e  = ek >> 9;
    int k  = ek & 511;
    float f[4] = {v.x, v.y, v.z, v.w};
    __nv_bfloat16 hi[4], lo[4];
#pragma unroll
    for (int i = 0; i < 4; i++) {
        hi[i] = __float2bfloat16_rn(f[i]);
        lo[i] = __float2bfloat16_rn(f[i] - __bfloat162float(hi[i]));
    }
    uint2 h = make_uint2(pack_bf2(hi[0], hi[1]), pack_bf2(hi[2], hi[3]));
    uint2 l = make_uint2(pack_bf2(lo[0], lo[1]), pack_bf2(lo[2], lo[3]));
    size_t eb = (size_t)e << 20;        // e * 1024 * 1024
    *reinterpret_cast<uint2*>(g_B2 + eb + (size_t)k * 1024 + n)         = h;
    *reinterpret_cast<uint2*>(g_B2 + eb + (size_t)(512 + k) * 1024 + n) = l;
}

// ---------------- kernel 3: HMMA grouped GEMM -> g_y (scaled) ---------------
// CTA tile 128(M) x 128(N), 4 warps (2x2 of 64x64), K-step 32 orig K.
// SMEM/stage: Ahi 8K | Alo 8K | Bhi 8K | Blo 8K = 32KB; 3 stages = 96KB.
// => 2 CTAs resident per SM (finer wave quantization + cross-CTA latency hiding)
#define STG_BYTES 32768u
#define OA_HI 0u
#define OA_LO 8192u
#define OB_HI 16384u
#define OB_LO 24576u
#define GEMM_SMEM (3u * STG_BYTES)

// A smem: [128 rows][32 bf16], 64B rows, quad q(0..3):  phys = row*64  + ((q^((row>>1)&3))<<4)
// B smem: [32 rows(k)][128 bf16(n)], 256B rows, q(0..15): phys = row*256 + ((q^(row&7))<<4)
__global__ void __launch_bounds__(128, 2) moe_gemm_kernel(
    const int*   __restrict__ splits,
    const float* __restrict__ in_scale,
    const float* __restrict__ w_scale,
    const float* __restrict__ ovs)
{
    extern __shared__ char smem[];
    const uint32_t sb = smem_u32(smem);
    const int tid  = threadIdx.x;
    const int lane = tid & 31;
    const int wid  = tid >> 5;
    const int wm   = (wid & 1) * 64;    // warp M offset in tile
    const int wn   = (wid >> 1) * 64;   // warp N offset in tile

    const int bn = blockIdx.x & 7;      // 8 n-tiles of 128
    const int bm = blockIdx.x >> 3;
    const int m0 = bm * 128, n0 = bn * 128;

    // expert for this row tile (tiles never straddle experts: splits % 128 == 0)
    int e = 0;
    {
        int acc = 0;
#pragma unroll
        for (int i = 0; i < NEXP; i++) { acc += splits[i]; if (m0 < acc) { e = i; break; } }
    }
    const __nv_bfloat16* Ab = g_A2 + (size_t)m0 * 1024;
    const __nv_bfloat16* Bb = g_B2 + ((size_t)e << 20) + n0;

    // ---- stage loader (128 threads) ----
    auto load_stage = [&](int c) {            // c = k-step index 0..15
        const uint32_t s = sb + (uint32_t)(c % 3) * STG_BYTES;
        const int koff = c * 32;
        // A: 512 x16B units per half; 4 per thread
#pragma unroll
        for (int j = 0; j < 4; j++) {
            int u = tid + j * 128;
            int row = u >> 2, q = u & 3;
            uint32_t d = (uint32_t)(row * 64 + ((q ^ ((row >> 1) & 3)) << 4));
            const __nv_bfloat16* src = Ab + (size_t)row * 1024 + koff + q * 8;
            cp16(s + OA_HI + d, src);
            cp16(s + OA_LO + d, src + 512);
        }
        // B: 512 x16B units per half; 4 per thread
#pragma unroll
        for (int j = 0; j < 4; j++) {
            int u = tid + j * 128;
            int row = u >> 4, q = u & 15;
            uint32_t d = (uint32_t)(row * 256 + ((q ^ (row & 7)) << 4));
            const __nv_bfloat16* src = Bb + (size_t)(koff + row) * 1024 + q * 8;
            cp16(s + OB_HI + d, src);
            cp16(s + OB_LO + d, src + (size_t)512 * 1024);
        }
        cp_commit();
    };

    float c[4][8][4];
#pragma unroll
    for (int i = 0; i < 4; i++)
#pragma unroll
        for (int j = 0; j < 8; j++)
#pragma unroll
            for (int q = 0; q < 4; q++) c[i][j][q] = 0.f;

    load_stage(0);
    load_stage(1);

#pragma unroll 1
    for (int ks = 0; ks < 16; ks++) {
        cp_wait<1>();
        __syncthreads();
        if (ks + 2 < 16) load_stage(ks + 2);

        const uint32_t s = sb + (uint32_t)(ks % 3) * STG_BYTES;
#pragma unroll
        for (int kh = 0; kh < 32; kh += 16) {
            // ---- load ALL fragments up-front (no mid-chain ldsm stall) ----
            uint32_t a_hi[4][4], a_lo[4][4];
            {
                int row = (lane & 15);
                int kq  = (kh >> 3) + (lane >> 4);
#pragma unroll
                for (int i = 0; i < 4; i++) {
                    int r = wm + i * 16 + row;
                    uint32_t ad = (uint32_t)(r * 64 + ((kq ^ ((r >> 1) & 3)) << 4));
                    ldsm_x4(a_hi[i], s + OA_HI + ad);
                    ldsm_x4(a_lo[i], s + OA_LO + ad);
                }
            }
            uint32_t b_hi[4][4], b_lo[4][4];   // j-th x4 covers n-tiles 2j, 2j+1
            {
                int k   = kh + (lane & 15);
                int nqb = (wn >> 3) + (lane >> 4);
#pragma unroll
                for (int j = 0; j < 4; j++) {
                    int nq = nqb + j * 2;
                    uint32_t ad = (uint32_t)(k * 256 + ((nq ^ (k & 7)) << 4));
                    ldsm_x4_t(b_hi[j], s + OB_HI + ad);
                    ldsm_x4_t(b_lo[j], s + OB_LO + ad);
                }
            }
            // ---- 96 MMAs: hi*hi, lo*hi, hi*lo ----
#pragma unroll
            for (int i = 0; i < 4; i++)
#pragma unroll
                for (int j = 0; j < 8; j++)
                    mma16816(c[i][j], a_hi[i], &b_hi[j >> 1][(j & 1) * 2]);
#pragma unroll
            for (int i = 0; i < 4; i++)
#pragma unroll
                for (int j = 0; j < 8; j++)
                    mma16816(c[i][j], a_lo[i], &b_hi[j >> 1][(j & 1) * 2]);
#pragma unroll
            for (int i = 0; i < 4; i++)
#pragma unroll
                for (int j = 0; j < 8; j++)
                    mma16816(c[i][j], a_hi[i], &b_lo[j >> 1][(j & 1) * 2]);
        }
    }

    // ---- epilogue: scale rows, store fp32 scratch ----
    const float gs = in_scale[0] * w_scale[e];
#pragma unroll
    for (int i = 0; i < 4; i++) {
        int r0 = m0 + wm + i * 16 + (lane >> 2);
        float s0 = gs * ovs[r0];
        float s1 = gs * ovs[r0 + 8];
        float* y0 = g_y + (size_t)r0 * NN + n0 + wn + (lane & 3) * 2;
        float* y1 = y0 + (size_t)8 * NN;
#pragma unroll
        for (int j = 0; j < 8; j++) {
            float2 v0 = make_float2(c[i][j][0] * s0, c[i][j][1] * s0);
            float2 v1 = make_float2(c[i][j][2] * s1, c[i][j][3] * s1);
            *reinterpret_cast<float2*>(y0 + j * 8) = v0;
            *reinterpret_cast<float2*>(y1 + j * 8) = v1;
        }
    }
}

// ---------------- kernel 4: topk gather-reduce ------------------------------
__global__ void gather_kernel(const int* __restrict__ sidx,
                              float* __restrict__ out) {
    int t  = blockIdx.x;
    int n4 = threadIdx.x;
    int s0 = sidx[t * TOPK + 0];
    int s1 = sidx[t * TOPK + 1];
    const float4 a = *reinterpret_cast<const float4*>(g_y + (size_t)s0 * NN + n4 * 4);
    const float4 b = *reinterpret_cast<const float4*>(g_y + (size_t)s1 * NN + n4 * 4);
    float4 o;
    o.x = a.x + b.x; o.y = a.y + b.y; o.z = a.z + b.z; o.w = a.w + b.w;
    *reinterpret_cast<float4*>(out + (size_t)t * NN + n4 * 4) = o;
}

// ---------------- launch ----------------
extern "C" void kernel_launch(void* const* d_in, const int* in_sizes, int n_in,
                              void* d_out, int out_size) {
    (void)in_sizes; (void)n_in; (void)out_size;
    const float* input    = (const float*)d_in[0];
    const float* weight   = (const float*)d_in[1];
    const int*   splits   = (const int*)  d_in[2];
    const int*   scatter  = (const int*)  d_in[3];
    const float* in_scale = (const float*)d_in[4];
    const float* w_scale  = (const float*)d_in[5];
    const float* ovs      = (const float*)d_in[6];
    float*       out      = (float*)d_out;

    static bool attr_set = false;
    if (!attr_set) {
        cudaFuncSetAttribute(moe_gemm_kernel,
                             cudaFuncAttributeMaxDynamicSharedMemorySize,
                             (int)GEMM_SMEM);
        attr_set = true;
    }

    prep_input_kernel <<<(MM * KK / 4) / 256, 256>>>(input);
    prep_weight_kernel<<<(NEXP * KK * NN / 4) / 256, 256>>>(weight);
    moe_gemm_kernel   <<<(MM / 128) * (NN / 128), 128, GEMM_SMEM>>>(
        splits, in_scale, w_scale, ovs);
    gather_kernel     <<<NTOK, 256>>>(scatter, out);
}

// round 6
// speedup vs baseline: 1.2172x; 1.0784x over previous
#include <cuda_runtime.h>
#include <cuda_bf16.h>
#include <cstdint>

// ---------------- problem dims ----------------
#define NTOK 8192
#define TOPK 2
#define NEXP 8
#define MM   16384   // expert-sorted rows
#define KK   512
#define NN   1024

// g_A: [M][512]  tf32 (u32)        = 32 MiB
// g_B: [E][N][K] tf32 (u32), n-major (transposed weight) = 16 MiB
// g_y: [M][N]    f32 scratch       = 64 MiB
static __device__ __align__(128) uint32_t g_A[(size_t)MM * KK];
static __device__ __align__(128) uint32_t g_B[(size_t)NEXP * NN * KK];
static __device__ __align__(128) float    g_y[(size_t)MM * NN];

// ---------------- helpers ----------------
__device__ __forceinline__ uint32_t smem_u32(const void* p) {
    uint32_t a;
    asm("{ .reg .u64 t; cvta.to.shared.u64 t, %1; cvt.u32.u64 %0, t; }"
        : "=r"(a) : "l"(p));
    return a;
}
__device__ __forceinline__ void cp16(uint32_t dst, const void* src) {
    asm volatile("cp.async.cg.shared.global [%0], [%1], 16;"
                 :: "r"(dst), "l"(src) : "memory");
}
__device__ __forceinline__ void cp_commit() {
    asm volatile("cp.async.commit_group;" ::: "memory");
}
template <int N_>
__device__ __forceinline__ void cp_wait() {
    asm volatile("cp.async.wait_group %0;" :: "n"(N_) : "memory");
}
__device__ __forceinline__ void ldsm_x4(uint32_t* r, uint32_t addr) {
    asm volatile("ldmatrix.sync.aligned.m8n8.x4.shared.b16 {%0,%1,%2,%3}, [%4];"
                 : "=r"(r[0]), "=r"(r[1]), "=r"(r[2]), "=r"(r[3]) : "r"(addr));
}
// m16n8k8 tf32 MMA, fp32 accum
__device__ __forceinline__ void mma_tf32(float* c, const uint32_t* a,
                                         uint32_t b0, uint32_t b1) {
    asm volatile(
        "mma.sync.aligned.m16n8k8.row.col.f32.tf32.tf32.f32 "
        "{%0,%1,%2,%3}, {%4,%5,%6,%7}, {%8,%9}, {%0,%1,%2,%3};"
        : "+f"(c[0]), "+f"(c[1]), "+f"(c[2]), "+f"(c[3])
        : "r"(a[0]), "r"(a[1]), "r"(a[2]), "r"(a[3]), "r"(b0), "r"(b1));
}
__device__ __forceinline__ uint32_t f2tf32(float f) {
    uint32_t o;
    asm("cvt.rna.tf32.f32 %0, %1;" : "=r"(o) : "f"(f));
    return o;
}

// ---------------- kernel 1: input fp32 -> tf32 ------------------------------
__global__ void prep_input_kernel(const float* __restrict__ in) {
    size_t idx  = (size_t)blockIdx.x * blockDim.x + threadIdx.x; // MM*KK/4
    size_t base = idx * 4;
    float4 v = *reinterpret_cast<const float4*>(in + base);
    uint4 o = make_uint4(f2tf32(v.x), f2tf32(v.y), f2tf32(v.z), f2tf32(v.w));
    *reinterpret_cast<uint4*>(g_A + base) = o;
}

// ---------------- kernel 2: weight [E,K,N] fp32 -> [E,N,K] tf32 (transpose) -
__global__ void prep_weight_kernel(const float* __restrict__ w) {
    __shared__ float t[32][33];
    int b  = blockIdx.x;          // E*16*32 = 4096 blocks
    int e  = b >> 9;
    int r  = b & 511;
    int kc = r >> 5;              // 0..15 (32-wide K block)
    int nb = r & 31;              // 0..31 (32-wide N block)
    int tx = threadIdx.x, ty = threadIdx.y;
    t[ty][tx] = w[((size_t)e * KK + kc * 32 + ty) * NN + nb * 32 + tx];
    __syncthreads();
    float x = t[tx][ty];          // = w[e][kc*32+tx][nb*32+ty]
    g_B[((size_t)e * NN + nb * 32 + ty) * KK + kc * 32 + tx] = f2tf32(x);
}

// ---------------- kernel 3: tf32 HMMA grouped GEMM -> g_y (scaled) ----------
// CTA tile 128(M) x 128(N), 4 warps (2x2 of 64x64), K-step 32 (tf32).
// SMEM/stage: A 16K | B 16K = 32KB; 3 stages = 96KB -> 2 CTAs/SM.
#define STG_BYTES 32768u
#define OA 0u
#define OB 16384u
#define GEMM_SMEM (3u * STG_BYTES)

// smem tiles: [128 rows][32 tf32] = 128B rows, 8 quads; phys quad = q ^ (row&7)
__global__ void __launch_bounds__(128, 2) moe_gemm_kernel(
    const int*   __restrict__ splits,
    const float* __restrict__ in_scale,
    const float* __restrict__ w_scale,
    const float* __restrict__ ovs)
{
    extern __shared__ char smem[];
    const uint32_t sb = smem_u32(smem);
    const int tid  = threadIdx.x;
    const int lane = tid & 31;
    const int wid  = tid >> 5;
    const int wm   = (wid & 1) * 64;    // warp M offset
    const int wn   = (wid >> 1) * 64;   // warp N offset

    const int bn = blockIdx.x & 7;
    const int bm = blockIdx.x >> 3;
    const int m0 = bm * 128, n0 = bn * 128;

    int e = 0;
    {
        int acc = 0;
#pragma unroll
        for (int i = 0; i < NEXP; i++) { acc += splits[i]; if (m0 < acc) { e = i; break; } }
    }
    const char* Ag = (const char*)(g_A + (size_t)m0 * KK);
    const char* Bg = (const char*)(g_B + ((size_t)e * NN + n0) * KK);

    // ---- stage loader: A 1024 + B 1024 16B-units, 8+8 per thread ----
    auto load_stage = [&](int c) {            // c = k-step 0..15
        const uint32_t s = sb + (uint32_t)(c % 3) * STG_BYTES;
        const uint32_t kb = (uint32_t)c * 128; // byte offset in 2048B row
#pragma unroll
        for (int j = 0; j < 8; j++) {
            int u = tid + j * 128;
            int row = u >> 3, q = u & 7;
            uint32_t d = (uint32_t)(row * 128 + ((q ^ (row & 7)) << 4));
            cp16(s + OA + d, Ag + (size_t)row * 2048 + kb + q * 16);
        }
#pragma unroll
        for (int j = 0; j < 8; j++) {
            int u = tid + j * 128;
            int row = u >> 3, q = u & 7;
            uint32_t d = (uint32_t)(row * 128 + ((q ^ (row & 7)) << 4));
            cp16(s + OB + d, Bg + (size_t)row * 2048 + kb + q * 16);
        }
        cp_commit();
    };

    float c[4][8][4];
#pragma unroll
    for (int i = 0; i < 4; i++)
#pragma unroll
        for (int j = 0; j < 8; j++)
#pragma unroll
            for (int q = 0; q < 4; q++) c[i][j][q] = 0.f;

    load_stage(0);
    load_stage(1);

    const int rl = lane & 15;
    const int qh = lane >> 4;                 // 0/1 -> k-half of ldmatrix x4

#pragma unroll 1
    for (int ks = 0; ks < 16; ks++) {
        cp_wait<1>();
        __syncthreads();
        if (ks + 2 < 16) load_stage(ks + 2);

        const uint32_t s = sb + (uint32_t)(ks % 3) * STG_BYTES;
#pragma unroll
        for (int su = 0; su < 4; su++) {      // k8 sub-steps within 32-wide stage
            const int q = 2 * su + qh;
            // A frags: x4 per m-tile (16x8 tf32 viewed as 16x16 b16)
            uint32_t a[4][4];
#pragma unroll
            for (int i = 0; i < 4; i++) {
                int row = wm + 16 * i + rl;
                ldsm_x4(a[i], s + OA + (uint32_t)(row * 128 + ((q ^ (row & 7)) << 4)));
            }
            // B frags: x4 #u covers n-tiles 2u (regs 0,2) and 2u+1 (regs 1,3)
            uint32_t b[4][4];
#pragma unroll
            for (int u = 0; u < 4; u++) {
                int row = wn + 16 * u + rl;
                ldsm_x4(b[u], s + OB + (uint32_t)(row * 128 + ((q ^ (row & 7)) << 4)));
            }
            // 32 MMAs
#pragma unroll
            for (int i = 0; i < 4; i++)
#pragma unroll
                for (int j = 0; j < 8; j++)
                    mma_tf32(c[i][j], a[i], b[j >> 1][j & 1], b[j >> 1][2 + (j & 1)]);
        }
    }

    // ---- epilogue: scale rows, store fp32 scratch ----
    const float gs = in_scale[0] * w_scale[e];
#pragma unroll
    for (int i = 0; i < 4; i++) {
        int r0 = m0 + wm + i * 16 + (lane >> 2);
        float s0 = gs * ovs[r0];
        float s1 = gs * ovs[r0 + 8];
        float* y0 = g_y + (size_t)r0 * NN + n0 + wn + (lane & 3) * 2;
        float* y1 = y0 + (size_t)8 * NN;
#pragma unroll
        for (int j = 0; j < 8; j++) {
            float2 v0 = make_float2(c[i][j][0] * s0, c[i][j][1] * s0);
            float2 v1 = make_float2(c[i][j][2] * s1, c[i][j][3] * s1);
            *reinterpret_cast<float2*>(y0 + j * 8) = v0;
            *reinterpret_cast<float2*>(y1 + j * 8) = v1;
        }
    }
}

// ---------------- kernel 4: topk gather-reduce ------------------------------
__global__ void gather_kernel(const int* __restrict__ sidx,
                              float* __restrict__ out) {
    int t  = blockIdx.x;
    int n4 = threadIdx.x;
    int s0 = sidx[t * TOPK + 0];
    int s1 = sidx[t * TOPK + 1];
    const float4 a = *reinterpret_cast<const float4*>(g_y + (size_t)s0 * NN + n4 * 4);
    const float4 b = *reinterpret_cast<const float4*>(g_y + (size_t)s1 * NN + n4 * 4);
    float4 o;
    o.x = a.x + b.x; o.y = a.y + b.y; o.z = a.z + b.z; o.w = a.w + b.w;
    *reinterpret_cast<float4*>(out + (size_t)t * NN + n4 * 4) = o;
}

// ---------------- launch ----------------
extern "C" void kernel_launch(void* const* d_in, const int* in_sizes, int n_in,
                              void* d_out, int out_size) {
    (void)in_sizes; (void)n_in; (void)out_size;
    const float* input    = (const float*)d_in[0];
    const float* weight   = (const float*)d_in[1];
    const int*   splits   = (const int*)  d_in[2];
    const int*   scatter  = (const int*)  d_in[3];
    const float* in_scale = (const float*)d_in[4];
    const float* w_scale  = (const float*)d_in[5];
    const float* ovs      = (const float*)d_in[6];
    float*       out      = (float*)d_out;

    static bool attr_set = false;
    if (!attr_set) {
        cudaFuncSetAttribute(moe_gemm_kernel,
                             cudaFuncAttributeMaxDynamicSharedMemorySize,
                             (int)GEMM_SMEM);
        attr_set = true;
    }

    prep_input_kernel <<<(MM * KK / 4) / 256, 256>>>(input);
    prep_weight_kernel<<<NEXP * (KK / 32) * (NN / 32), dim3(32, 32)>>>(weight);
    moe_gemm_kernel   <<<(MM / 128) * (NN / 128), 128, GEMM_SMEM>>>(
        splits, in_scale, w_scale, ovs);
    gather_kernel     <<<NTOK, 256>>>(scatter, out);
}

// round 10
// speedup vs baseline: 1.3463x; 1.1061x over previous
#include <cuda_runtime.h>
#include <cuda_bf16.h>
#include <cstdint>

// ---------------- problem dims ----------------
#define NTOK 8192
#define TOPK 2
#define NEXP 8
#define MM   16384   // expert-sorted rows
#define KK   512
#define NN   1024
#define NTILE ((MM / 128) * (NN / 128))   // 1024
#define NPERS 296                         // persistent CTAs (2 per SM)

// g_A: [M][512]  tf32 (u32)        = 32 MiB
// g_B: [E][N][K] tf32 (u32), n-major (transposed weight) = 16 MiB
// g_y: [M][N]    f32 scratch       = 64 MiB
static __device__ __align__(128) uint32_t g_A[(size_t)MM * KK];
static __device__ __align__(128) uint32_t g_B[(size_t)NEXP * NN * KK];
static __device__ __align__(128) float    g_y[(size_t)MM * NN];

// ---------------- helpers ----------------
__device__ __forceinline__ uint32_t smem_u32(const void* p) {
    uint32_t a;
    asm("{ .reg .u64 t; cvta.to.shared.u64 t, %1; cvt.u32.u64 %0, t; }"
        : "=r"(a) : "l"(p));
    return a;
}
__device__ __forceinline__ void cp16(uint32_t dst, const void* src) {
    asm volatile("cp.async.cg.shared.global [%0], [%1], 16;"
                 :: "r"(dst), "l"(src) : "memory");
}
__device__ __forceinline__ void cp_commit() {
    asm volatile("cp.async.commit_group;" ::: "memory");
}
template <int N_>
__device__ __forceinline__ void cp_wait() {
    asm volatile("cp.async.wait_group %0;" :: "n"(N_) : "memory");
}
__device__ __forceinline__ void ldsm_x4(uint32_t* r, uint32_t addr) {
    asm volatile("ldmatrix.sync.aligned.m8n8.x4.shared.b16 {%0,%1,%2,%3}, [%4];"
                 : "=r"(r[0]), "=r"(r[1]), "=r"(r[2]), "=r"(r[3]) : "r"(addr));
}
// m16n8k8 tf32 MMA, fp32 accum
__device__ __forceinline__ void mma_tf32(float* c, const uint32_t* a,
                                         uint32_t b0, uint32_t b1) {
    asm volatile(
        "mma.sync.aligned.m16n8k8.row.col.f32.tf32.tf32.f32 "
        "{%0,%1,%2,%3}, {%4,%5,%6,%7}, {%8,%9}, {%0,%1,%2,%3};"
        : "+f"(c[0]), "+f"(c[1]), "+f"(c[2]), "+f"(c[3])
        : "r"(a[0]), "r"(a[1]), "r"(a[2]), "r"(a[3]), "r"(b0), "r"(b1));
}
__device__ __forceinline__ uint32_t f2tf32(float f) {
    uint32_t o;
    asm("cvt.rna.tf32.f32 %0, %1;" : "=r"(o) : "f"(f));
    return o;
}

// ---------------- kernel 1: fused prep (input + weight) ---------------------
// blocks [0, 8192): input fp32 -> tf32 (flat, 1024 elems/block)
// blocks [8192, 12288): weight [E,K,N] -> [E,N,K] tf32, 32x32 smem transpose
#define PREP_IN_BLOCKS 8192
__global__ void prep_kernel(const float* __restrict__ in,
                            const float* __restrict__ w) {
    __shared__ float t[32][33];
    int b = blockIdx.x;
    int tid = threadIdx.x;
    if (b < PREP_IN_BLOCKS) {
        size_t base = ((size_t)b * 256 + tid) * 4;
        float4 v = *reinterpret_cast<const float4*>(in + base);
        uint4 o = make_uint4(f2tf32(v.x), f2tf32(v.y), f2tf32(v.z), f2tf32(v.w));
        *reinterpret_cast<uint4*>(g_A + base) = o;
    } else {
        int r  = b - PREP_IN_BLOCKS;      // E*16*32 = 4096 blocks
        int e  = r >> 9;
        int rr = r & 511;
        int kc = rr >> 5;                 // 32-wide K block
        int nb = rr & 31;                 // 32-wide N block
        int tx = tid & 31, ty0 = tid >> 5; // 8 rows per pass
#pragma unroll
        for (int p = 0; p < 4; p++) {
            int ty = ty0 + p * 8;
            t[ty][tx] = w[((size_t)e * KK + kc * 32 + ty) * NN + nb * 32 + tx];
        }
        __syncthreads();
#pragma unroll
        for (int p = 0; p < 4; p++) {
            int ty = ty0 + p * 8;
            float x = t[tx][ty];          // = w[e][kc*32+tx][nb*32+ty]
            g_B[((size_t)e * NN + nb * 32 + ty) * KK + kc * 32 + tx] = f2tf32(x);
        }
    }
}

// ---------------- kernel 2: persistent tf32 HMMA grouped GEMM ---------------
// CTA tile 128x128, 4 warps (2x2 of 64x64), K-step 32 tf32 per chunk,
// 16 chunks per tile. 296 persistent CTAs; ONE continuous 3-slot cp.async
// pipeline over the global chunk stream g = tile*16 + ks (crosses tile
// boundaries -> no per-tile fill/drain).
#define STG_BYTES 32768u
#define OA 0u
#define OB 16384u
#define GEMM_SMEM (3u * STG_BYTES)

// smem tiles: [128 rows][32 tf32] = 128B rows, 8 quads; phys quad = q ^ (row&7)
__global__ void __launch_bounds__(128, 2) moe_gemm_kernel(
    const int*   __restrict__ splits,
    const float* __restrict__ in_scale,
    const float* __restrict__ w_scale,
    const float* __restrict__ ovs)
{
    extern __shared__ char smem[];
    const uint32_t sb = smem_u32(smem);
    const int tid  = threadIdx.x;
    const int lane = tid & 31;
    const int wid  = tid >> 5;
    const int wm   = (wid & 1) * 64;    // warp M offset
    const int wn   = (wid >> 1) * 64;   // warp N offset

    const int bid   = blockIdx.x;
    const int nt    = (NTILE - bid + NPERS - 1) / NPERS;  // tiles for this CTA
    const int total = nt * 16;                            // chunks for this CTA

    // ---- loader-side tile pointers (refreshed when ks==0 of load cursor) ----
    const char* Ag = nullptr;
    const char* Bg = nullptr;
    auto set_tile = [&](int ti) {
        int tile = bid + ti * NPERS;
        int m0 = (tile >> 3) * 128;
        int n0 = (tile & 7) * 128;
        int e = 0, acc = 0;
#pragma unroll
        for (int i = 0; i < NEXP; i++) { acc += splits[i]; if (m0 < acc) { e = i; break; } }
        Ag = (const char*)(g_A + (size_t)m0 * KK);
        Bg = (const char*)(g_B + ((size_t)e * NN + n0) * KK);
    };

    auto load_g = [&](int g) {
        int ks = g & 15;
        if (ks == 0) set_tile(g >> 4);
        const uint32_t s  = sb + (uint32_t)(g % 3) * STG_BYTES;
        const uint32_t kb = (uint32_t)ks * 128;   // byte offset in 2048B row
#pragma unroll
        for (int j = 0; j < 8; j++) {
            int u = tid + j * 128;
            int row = u >> 3, q = u & 7;
            uint32_t d = (uint32_t)(row * 128 + ((q ^ (row & 7)) << 4));
            cp16(s + OA + d, Ag + (size_t)row * 2048 + kb + q * 16);
        }
#pragma unroll
        for (int j = 0; j < 8; j++) {
            int u = tid + j * 128;
            int row = u >> 3, q = u & 7;
            uint32_t d = (uint32_t)(row * 128 + ((q ^ (row & 7)) << 4));
            cp16(s + OB + d, Bg + (size_t)row * 2048 + kb + q * 16);
        }
        cp_commit();
    };

    float c[4][8][4];
#pragma unroll
    for (int i = 0; i < 4; i++)
#pragma unroll
        for (int j = 0; j < 8; j++)
#pragma unroll
            for (int q = 0; q < 4; q++) c[i][j][q] = 0.f;

    load_g(0);
    if (total > 1) load_g(1);

    const int rl = lane & 15;
    const int qh = lane >> 4;                 // 0/1 -> k-half of ldmatrix x4

#pragma unroll 1
    for (int g = 0; g < total; g++) {
        cp_wait<1>();
        __syncthreads();
        if (g + 2 < total) load_g(g + 2);

        const uint32_t s = sb + (uint32_t)(g % 3) * STG_BYTES;
#pragma unroll
        for (int su = 0; su < 4; su++) {      // k8 sub-steps within 32-wide chunk
            const int q = 2 * su + qh;
            uint32_t a[4][4];
#pragma unroll
            for (int i = 0; i < 4; i++) {
                int row = wm + 16 * i + rl;
                ldsm_x4(a[i], s + OA + (uint32_t)(row * 128 + ((q ^ (row & 7)) << 4)));
            }
            uint32_t b[4][4];
#pragma unroll
            for (int u = 0; u < 4; u++) {
                int row = wn + 16 * u + rl;
                ldsm_x4(b[u], s + OB + (uint32_t)(row * 128 + ((q ^ (row & 7)) << 4)));
            }
#pragma unroll
            for (int i = 0; i < 4; i++)
#pragma unroll
                for (int j = 0; j < 8; j++)
                    mma_tf32(c[i][j], a[i], b[j >> 1][j & 1], b[j >> 1][2 + (j & 1)]);
        }

        // ---- tile finished: epilogue + accumulator reset ----
        if ((g & 15) == 15) {
            int tile = bid + (g >> 4) * NPERS;
            int m0 = (tile >> 3) * 128;
            int n0 = (tile & 7) * 128;
            int e = 0, acc = 0;
#pragma unroll
            for (int i = 0; i < NEXP; i++) { acc += splits[i]; if (m0 < acc) { e = i; break; } }
            const float gs = in_scale[0] * w_scale[e];
#pragma unroll
            for (int i = 0; i < 4; i++) {
                int r0 = m0 + wm + i * 16 + (lane >> 2);
                float s0 = gs * ovs[r0];
                float s1 = gs * ovs[r0 + 8];
                float* y0 = g_y + (size_t)r0 * NN + n0 + wn + (lane & 3) * 2;
                float* y1 = y0 + (size_t)8 * NN;
#pragma unroll
                for (int j = 0; j < 8; j++) {
                    float2 v0 = make_float2(c[i][j][0] * s0, c[i][j][1] * s0);
                    float2 v1 = make_float2(c[i][j][2] * s1, c[i][j][3] * s1);
                    *reinterpret_cast<float2*>(y0 + j * 8) = v0;
                    *reinterpret_cast<float2*>(y1 + j * 8) = v1;
                }
            }
#pragma unroll
            for (int i = 0; i < 4; i++)
#pragma unroll
                for (int j = 0; j < 8; j++)
#pragma unroll
                    for (int q2 = 0; q2 < 4; q2++) c[i][j][q2] = 0.f;
        }
    }
}

// ---------------- kernel 3: topk gather-reduce ------------------------------
__global__ void gather_kernel(const int* __restrict__ sidx,
                              float* __restrict__ out) {
    int t  = blockIdx.x;
    int n4 = threadIdx.x;
    int s0 = sidx[t * TOPK + 0];
    int s1 = sidx[t * TOPK + 1];
    const float4 a = *reinterpret_cast<const float4*>(g_y + (size_t)s0 * NN + n4 * 4);
    const float4 b = *reinterpret_cast<const float4*>(g_y + (size_t)s1 * NN + n4 * 4);
    float4 o;
    o.x = a.x + b.x; o.y = a.y + b.y; o.z = a.z + b.z; o.w = a.w + b.w;
    *reinterpret_cast<float4*>(out + (size_t)t * NN + n4 * 4) = o;
}

// ---------------- launch ----------------
extern "C" void kernel_launch(void* const* d_in, const int* in_sizes, int n_in,
                              void* d_out, int out_size) {
    (void)in_sizes; (void)n_in; (void)out_size;
    const float* input    = (const float*)d_in[0];
    const float* weight   = (const float*)d_in[1];
    const int*   splits   = (const int*)  d_in[2];
    const int*   scatter  = (const int*)  d_in[3];
    const float* in_scale = (const float*)d_in[4];
    const float* w_scale  = (const float*)d_in[5];
    const float* ovs      = (const float*)d_in[6];
    float*       out      = (float*)d_out;

    static bool attr_set = false;
    if (!attr_set) {
        cudaFuncSetAttribute(moe_gemm_kernel,
                             cudaFuncAttributeMaxDynamicSharedMemorySize,
                             (int)GEMM_SMEM);
        attr_set = true;
    }

    prep_kernel     <<<PREP_IN_BLOCKS + NEXP * (KK / 32) * (NN / 32), 256>>>(input, weight);
    moe_gemm_kernel <<<NPERS, 128, GEMM_SMEM>>>(splits, in_scale, w_scale, ovs);
    gather_kernel   <<<NTOK, 256>>>(scatter, out);
}

// round 11
// speedup vs baseline: 1.4013x; 1.0408x over previous
#include <cuda_runtime.h>
#include <cuda_bf16.h>
#include <cstdint>

// ---------------- problem dims ----------------
#define NTOK 8192
#define TOPK 2
#define NEXP 8
#define MM   16384   // expert-sorted rows
#define KK   512
#define NN   1024
#define NTILE ((MM / 128) * (NN / 128))   // 1024
#define NPERS 296                         // persistent CTAs (2 per SM)

// g_B: [E][N][K] tf32 (u32), n-major (transposed weight) = 16 MiB
// g_y: [M][N]    f32 scratch                             = 64 MiB
static __device__ __align__(128) uint32_t g_B[(size_t)NEXP * NN * KK];
static __device__ __align__(128) float    g_y[(size_t)MM * NN];

// ---------------- helpers ----------------
__device__ __forceinline__ uint32_t smem_u32(const void* p) {
    uint32_t a;
    asm("{ .reg .u64 t; cvta.to.shared.u64 t, %1; cvt.u32.u64 %0, t; }"
        : "=r"(a) : "l"(p));
    return a;
}
__device__ __forceinline__ void cp16(uint32_t dst, const void* src) {
    asm volatile("cp.async.cg.shared.global [%0], [%1], 16;"
                 :: "r"(dst), "l"(src) : "memory");
}
__device__ __forceinline__ void cp_commit() {
    asm volatile("cp.async.commit_group;" ::: "memory");
}
template <int N_>
__device__ __forceinline__ void cp_wait() {
    asm volatile("cp.async.wait_group %0;" :: "n"(N_) : "memory");
}
__device__ __forceinline__ void ldsm_x4(uint32_t* r, uint32_t addr) {
    asm volatile("ldmatrix.sync.aligned.m8n8.x4.shared.b16 {%0,%1,%2,%3}, [%4];"
                 : "=r"(r[0]), "=r"(r[1]), "=r"(r[2]), "=r"(r[3]) : "r"(addr));
}
// m16n8k8 tf32 MMA, fp32 accum
__device__ __forceinline__ void mma_tf32(float* c, const uint32_t* a,
                                         uint32_t b0, uint32_t b1) {
    asm volatile(
        "mma.sync.aligned.m16n8k8.row.col.f32.tf32.tf32.f32 "
        "{%0,%1,%2,%3}, {%4,%5,%6,%7}, {%8,%9}, {%0,%1,%2,%3};"
        : "+f"(c[0]), "+f"(c[1]), "+f"(c[2]), "+f"(c[3])
        : "r"(a[0]), "r"(a[1]), "r"(a[2]), "r"(a[3]), "r"(b0), "r"(b1));
}
__device__ __forceinline__ uint32_t f2tf32(float f) {
    uint32_t o;
    asm("cvt.rna.tf32.f32 %0, %1;" : "=r"(o) : "f"(f));
    return o;
}
// in-register RNA rounding of fp32 bits -> tf32 bits (same op prep_input did)
__device__ __forceinline__ uint32_t tf32_rna_bits(uint32_t x) {
    uint32_t o;
    asm("cvt.rna.tf32.f32 %0, %1;" : "=r"(o) : "f"(__uint_as_float(x)));
    return o;
}

// ---------------- kernel 1: weight-only prep --------------------------------
// weight [E,K,N] fp32 -> g_B [E,N,K] tf32 (transpose + RNA round)
__global__ void prep_weight_kernel(const float* __restrict__ w) {
    __shared__ float t[32][33];
    int b  = blockIdx.x;              // E*16*32 = 4096 blocks
    int e  = b >> 9;
    int rr = b & 511;
    int kc = rr >> 5;                 // 32-wide K block
    int nb = rr & 31;                 // 32-wide N block
    int tid = threadIdx.x;
    int tx = tid & 31, ty0 = tid >> 5; // 8 rows per pass
#pragma unroll
    for (int p = 0; p < 4; p++) {
        int ty = ty0 + p * 8;
        t[ty][tx] = w[((size_t)e * KK + kc * 32 + ty) * NN + nb * 32 + tx];
    }
    __syncthreads();
#pragma unroll
    for (int p = 0; p < 4; p++) {
        int ty = ty0 + p * 8;
        float x = t[tx][ty];          // = w[e][kc*32+tx][nb*32+ty]
        g_B[((size_t)e * NN + nb * 32 + ty) * KK + kc * 32 + tx] = f2tf32(x);
    }
}

// ---------------- kernel 2: persistent tf32 HMMA grouped GEMM ---------------
// A is the RAW fp32 input (tf32 = fp32 bits; RNA rounding applied in-register
// after ldmatrix — identical math to the old prep_input path).
// CTA tile 128x128, 4 warps (2x2 of 64x64), K-step 32 per chunk, 16 chunks
// per tile, 296 persistent CTAs, continuous 3-slot cp.async ring crossing
// tile boundaries.
#define STG_BYTES 32768u
#define OA 0u
#define OB 16384u
#define GEMM_SMEM (3u * STG_BYTES)

// smem tiles: [128 rows][32 u32] = 128B rows, 8 quads; phys quad = q ^ (row&7)
__global__ void __launch_bounds__(128, 2) moe_gemm_kernel(
    const float* __restrict__ input,
    const int*   __restrict__ splits,
    const float* __restrict__ in_scale,
    const float* __restrict__ w_scale,
    const float* __restrict__ ovs)
{
    extern __shared__ char smem[];
    const uint32_t sb = smem_u32(smem);
    const int tid  = threadIdx.x;
    const int lane = tid & 31;
    const int wid  = tid >> 5;
    const int wm   = (wid & 1) * 64;    // warp M offset
    const int wn   = (wid >> 1) * 64;   // warp N offset

    const int bid   = blockIdx.x;
    const int nt    = (NTILE - bid + NPERS - 1) / NPERS;  // tiles for this CTA
    const int total = nt * 16;                            // chunks for this CTA

    // ---- loader-side tile pointers (refreshed when ks==0 of load cursor) ----
    const char* Ag = nullptr;
    const char* Bg = nullptr;
    auto set_tile = [&](int ti) {
        int tile = bid + ti * NPERS;
        int m0 = (tile >> 3) * 128;
        int n0 = (tile & 7) * 128;
        int e = 0, acc = 0;
#pragma unroll
        for (int i = 0; i < NEXP; i++) { acc += splits[i]; if (m0 < acc) { e = i; break; } }
        Ag = (const char*)(input + (size_t)m0 * KK);
        Bg = (const char*)(g_B + ((size_t)e * NN + n0) * KK);
    };

    auto load_g = [&](int g) {
        int ks = g & 15;
        if (ks == 0) set_tile(g >> 4);
        const uint32_t s  = sb + (uint32_t)(g % 3) * STG_BYTES;
        const uint32_t kb = (uint32_t)ks * 128;   // byte offset in 2048B row
#pragma unroll
        for (int j = 0; j < 8; j++) {
            int u = tid + j * 128;
            int row = u >> 3, q = u & 7;
            uint32_t d = (uint32_t)(row * 128 + ((q ^ (row & 7)) << 4));
            cp16(s + OA + d, Ag + (size_t)row * 2048 + kb + q * 16);
        }
#pragma unroll
        for (int j = 0; j < 8; j++) {
            int u = tid + j * 128;
            int row = u >> 3, q = u & 7;
            uint32_t d = (uint32_t)(row * 128 + ((q ^ (row & 7)) << 4));
            cp16(s + OB + d, Bg + (size_t)row * 2048 + kb + q * 16);
        }
        cp_commit();
    };

    float c[4][8][4];
#pragma unroll
    for (int i = 0; i < 4; i++)
#pragma unroll
        for (int j = 0; j < 8; j++)
#pragma unroll
            for (int q = 0; q < 4; q++) c[i][j][q] = 0.f;

    load_g(0);
    if (total > 1) load_g(1);

    const int rl = lane & 15;
    const int qh = lane >> 4;                 // 0/1 -> k-half of ldmatrix x4

#pragma unroll 1
    for (int g = 0; g < total; g++) {
        cp_wait<1>();
        __syncthreads();
        if (g + 2 < total) load_g(g + 2);

        const uint32_t s = sb + (uint32_t)(g % 3) * STG_BYTES;
#pragma unroll
        for (int su = 0; su < 4; su++) {      // k8 sub-steps within 32-wide chunk
            const int q = 2 * su + qh;
            uint32_t a[4][4];
#pragma unroll
            for (int i = 0; i < 4; i++) {
                int row = wm + 16 * i + rl;
                ldsm_x4(a[i], s + OA + (uint32_t)(row * 128 + ((q ^ (row & 7)) << 4)));
            }
            // RNA-round A fragments fp32 -> tf32 (same op the old prep did)
#pragma unroll
            for (int i = 0; i < 4; i++)
#pragma unroll
                for (int r2 = 0; r2 < 4; r2++)
                    a[i][r2] = tf32_rna_bits(a[i][r2]);
            uint32_t b[4][4];
#pragma unroll
            for (int u = 0; u < 4; u++) {
                int row = wn + 16 * u + rl;
                ldsm_x4(b[u], s + OB + (uint32_t)(row * 128 + ((q ^ (row & 7)) << 4)));
            }
#pragma unroll
            for (int i = 0; i < 4; i++)
#pragma unroll
                for (int j = 0; j < 8; j++)
                    mma_tf32(c[i][j], a[i], b[j >> 1][j & 1], b[j >> 1][2 + (j & 1)]);
        }

        // ---- tile finished: epilogue + accumulator reset ----
        if ((g & 15) == 15) {
            int tile = bid + (g >> 4) * NPERS;
            int m0 = (tile >> 3) * 128;
            int n0 = (tile & 7) * 128;
            int e = 0, acc = 0;
#pragma unroll
            for (int i = 0; i < NEXP; i++) { acc += splits[i]; if (m0 < acc) { e = i; break; } }
            const float gs = in_scale[0] * w_scale[e];
#pragma unroll
            for (int i = 0; i < 4; i++) {
                int r0 = m0 + wm + i * 16 + (lane >> 2);
                float s0 = gs * ovs[r0];
                float s1 = gs * ovs[r0 + 8];
                float* y0 = g_y + (size_t)r0 * NN + n0 + wn + (lane & 3) * 2;
                float* y1 = y0 + (size_t)8 * NN;
#pragma unroll
                for (int j = 0; j < 8; j++) {
                    float2 v0 = make_float2(c[i][j][0] * s0, c[i][j][1] * s0);
                    float2 v1 = make_float2(c[i][j][2] * s1, c[i][j][3] * s1);
                    *reinterpret_cast<float2*>(y0 + j * 8) = v0;
                    *reinterpret_cast<float2*>(y1 + j * 8) = v1;
                }
            }
#pragma unroll
            for (int i = 0; i < 4; i++)
#pragma unroll
                for (int j = 0; j < 8; j++)
#pragma unroll
                    for (int q2 = 0; q2 < 4; q2++) c[i][j][q2] = 0.f;
        }
    }
}

// ---------------- kernel 3: topk gather-reduce ------------------------------
__global__ void gather_kernel(const int* __restrict__ sidx,
                              float* __restrict__ out) {
    int t  = blockIdx.x;
    int n4 = threadIdx.x;
    int s0 = sidx[t * TOPK + 0];
    int s1 = sidx[t * TOPK + 1];
    const float4 a = *reinterpret_cast<const float4*>(g_y + (size_t)s0 * NN + n4 * 4);
    const float4 b = *reinterpret_cast<const float4*>(g_y + (size_t)s1 * NN + n4 * 4);
    float4 o;
    o.x = a.x + b.x; o.y = a.y + b.y; o.z = a.z + b.z; o.w = a.w + b.w;
    *reinterpret_cast<float4*>(out + (size_t)t * NN + n4 * 4) = o;
}

// ---------------- launch ----------------
extern "C" void kernel_launch(void* const* d_in, const int* in_sizes, int n_in,
                              void* d_out, int out_size) {
    (void)in_sizes; (void)n_in; (void)out_size;
    const float* input    = (const float*)d_in[0];
    const float* weight   = (const float*)d_in[1];
    const int*   splits   = (const int*)  d_in[2];
    const int*   scatter  = (const int*)  d_in[3];
    const float* in_scale = (const float*)d_in[4];
    const float* w_scale  = (const float*)d_in[5];
    const float* ovs      = (const float*)d_in[6];
    float*       out      = (float*)d_out;

    static bool attr_set = false;
    if (!attr_set) {
        cudaFuncSetAttribute(moe_gemm_kernel,
                             cudaFuncAttributeMaxDynamicSharedMemorySize,
                             (int)GEMM_SMEM);
        attr_set = true;
    }

    prep_weight_kernel<<<NEXP * (KK / 32) * (NN / 32), 256>>>(weight);
    moe_gemm_kernel   <<<NPERS, 128, GEMM_SMEM>>>(input, splits, in_scale, w_scale, ovs);
    gather_kernel     <<<NTOK, 256>>>(scatter, out);
}